// round 11
// baseline (speedup 1.0000x reference)
#include <cuda_runtime.h>
#include <cuda_bf16.h>
#include <math.h>
#include <cstdint>

#define BB 4
#define CC 64
#define OCH 64
#define HH 256
#define WW 256
#define PP 64
#define NBLK (BB * HH * (WW / PP))   // 4096

__device__ float g_psum  [OCH * NBLK];
__device__ float g_psumsq[OCH * NBLK];
__device__ float g_scale [OCH];
__device__ float g_shift [OCH];

// A fragments for mma.sync.m16n8k16: ks 0-3 = hi, ks 4-7 = lo (chain 3 reuses hi)
__device__ uint4  g_Apack2[12 * 12 * 32];   // pw  (192x64)
__device__ uint4  g_Apack4[ 4 * 12 * 32];   // w2  ( 64x64)
__device__ float4 g_dwpack[CC * 3];         // dw 3x3 rows padded to float4

#define BW 68
#define OM_OFF (64 * BW)                    // 4352 floats
#define SMEM_BYTES ((OM_OFF + 192 * BW) * 4)   // 69632 -> 3 CTAs/SM

__device__ __forceinline__ uint32_t bfpack(__nv_bfloat16 a, __nv_bfloat16 b) {
    return (uint32_t)__bfloat16_as_ushort(a) | ((uint32_t)__bfloat16_as_ushort(b) << 16);
}

__device__ __forceinline__ uint32_t wpack(const float* W, int r, int c, bool lo) {
    float v0 = W[r * 64 + c], v1 = W[r * 64 + c + 1];
    __nv_bfloat16 h0 = __float2bfloat16(v0), h1 = __float2bfloat16(v1);
    if (lo) {
        h0 = __float2bfloat16(v0 - __bfloat162float(h0));
        h1 = __float2bfloat16(v1 - __bfloat162float(h1));
    }
    return bfpack(h0, h1);
}

__global__ void prep_weights(const float* __restrict__ pw, const float* __restrict__ w2,
                             const float* __restrict__ dw)
{
    int idx = blockIdx.x * 256 + threadIdx.x;
    if (idx >= 6144) {                       // dw pack: 64 ch x 3 rows
        idx -= 6144;
        if (idx < CC * 3) {
            const int c = idx / 3, r = idx % 3;
            g_dwpack[idx] = make_float4(dw[c * 9 + r * 3], dw[c * 9 + r * 3 + 1],
                                        dw[c * 9 + r * 3 + 2], 0.0f);
        }
        return;
    }
    const float* W;
    uint4* dst;
    if (idx < 4608)      { W = pw; dst = g_Apack2; }
    else                 { idx -= 4608; W = w2; dst = g_Apack4; }
    const int mt = idx / 384;
    const int ks = (idx % 384) / 32;
    const int l  = idx % 32;
    const bool lo = ((ks >> 2) == 1);
    const int cb = (ks & 3) * 16 + (l & 3) * 2;
    const int r0 = mt * 16 + (l >> 2), r1 = r0 + 8;
    uint4 a;
    a.x = wpack(W, r0, cb,     lo);
    a.y = wpack(W, r1, cb,     lo);
    a.z = wpack(W, r0, cb + 8, lo);
    a.w = wpack(W, r1, cb + 8, lo);
    dst[idx] = a;
}

__device__ __forceinline__ void hmma(float d[4], uint4 a, uint32_t b0, uint32_t b1) {
    asm volatile(
        "mma.sync.aligned.m16n8k16.row.col.f32.bf16.bf16.f32 "
        "{%0,%1,%2,%3}, {%4,%5,%6,%7}, {%8,%9}, {%0,%1,%2,%3};"
        : "+f"(d[0]), "+f"(d[1]), "+f"(d[2]), "+f"(d[3])
        : "r"(a.x), "r"(a.y), "r"(a.z), "r"(a.w), "r"(b0), "r"(b1));
}

__device__ __forceinline__ float fetch_px(const float* __restrict__ img, int y, int x) {
    if ((unsigned)y < (unsigned)HH && (unsigned)x < (unsigned)WW)
        return __ldg(img + y * WW + x);
    return 0.0f;
}

__device__ __forceinline__ float sigm2(float v) {
    return __fdividef(2.0f, 1.0f + __expf(-v));
}

__global__ __launch_bounds__(256, 3)
void fused_deform_kernel(const float* __restrict__ x,
                         const float* __restrict__ bias,
                         float* __restrict__ out)
{
    extern __shared__ __align__(16) float sm[];
    uint32_t* sB   = (uint32_t*)sm;
    float*    s_om = sm + OM_OFF;
    float*    s_red  = s_om;
    float*    s_red2 = s_om + 256;

    const int tid  = threadIdx.x;
    const int wid  = tid >> 5;
    const int lane = tid & 31;
    const int w0   = blockIdx.x * PP;
    const int h    = blockIdx.y;
    const int b    = blockIdx.z;
    const int bid  = (blockIdx.z * gridDim.y + blockIdx.y) * gridDim.x + blockIdx.x;

    // ---- stage 1: depthwise conv -> bf16 hi/lo B tile ----------------------
    {
        const int g   = tid & 15;
        const int cb4 = (tid >> 4) * 4;
        const int xs  = w0 + g * 4;
        const bool lok = (xs - 1 >= 0);
        const bool rok = (xs + 4 < WW);
        const bool yok0 = (h - 1 >= 0);
        const bool yok2 = (h + 1 < HH);
        float val[4][4];
        #pragma unroll
        for (int u = 0; u < 4; u++) {
            const int c = cb4 + u;
            const float* xc = x + ((size_t)(b * CC + c)) * (HH * WW);
            float a0 = 0.f, a1 = 0.f, a2 = 0.f, a3 = 0.f;
            #pragma unroll
            for (int dy = -1; dy <= 1; dy++) {
                const bool yok = (dy == -1) ? yok0 : (dy == 1) ? yok2 : true;
                if (yok) {
                    const float* row = xc + (h + dy) * WW;
                    const float4 m = *reinterpret_cast<const float4*>(row + xs);
                    const float lm = lok ? __ldg(row + xs - 1) : 0.0f;
                    const float rm = rok ? __ldg(row + xs + 4) : 0.0f;
                    const float4 w3 = __ldg(&g_dwpack[c * 3 + dy + 1]);
                    a0 += w3.x * lm  + w3.y * m.x + w3.z * m.y;
                    a1 += w3.x * m.x + w3.y * m.y + w3.z * m.z;
                    a2 += w3.x * m.y + w3.y * m.z + w3.z * m.w;
                    a3 += w3.x * m.z + w3.y * m.w + w3.z * rm;
                }
            }
            val[u][0] = a0; val[u][1] = a1; val[u][2] = a2; val[u][3] = a3;
        }
        #pragma unroll
        for (int pr = 0; pr < 2; pr++)
            #pragma unroll
            for (int r = 0; r < 4; r++) {
                const int p = g * 4 + r;
                const float v0 = val[2 * pr][r], v1 = val[2 * pr + 1][r];
                const __nv_bfloat16 h0 = __float2bfloat16(v0);
                const __nv_bfloat16 h1 = __float2bfloat16(v1);
                const __nv_bfloat16 l0 = __float2bfloat16(v0 - __bfloat162float(h0));
                const __nv_bfloat16 l1 = __float2bfloat16(v1 - __bfloat162float(h1));
                sB[p * BW + (cb4 >> 1) + pr]      = bfpack(h0, h1);
                sB[p * BW + 32 + (cb4 >> 1) + pr] = bfpack(l0, l1);
            }
    }
    __syncthreads();

    const int rg = lane >> 2;
    const int qd = lane & 3;
    const int nthalf = wid >> 2;

    // ---- stage 2: om = pw @ t  (warp = 3 mt x 4 ntiles, B resident 2 nt) --
    {
        const int mt0 = 3 * (wid & 3);
        #pragma unroll 1
        for (int pass = 0; pass < 2; pass++) {
            uint32_t breg[2][16];
            #pragma unroll
            for (int ntl = 0; ntl < 2; ntl++) {
                const int nt = nthalf * 4 + pass * 2 + ntl;
                const uint32_t* bb = sB + (nt * 8 + rg) * BW + qd;
                #pragma unroll
                for (int k = 0; k < 4; k++) {
                    breg[ntl][2 * k]         = bb[k * 8];
                    breg[ntl][2 * k + 1]     = bb[k * 8 + 4];
                    breg[ntl][8 + 2 * k]     = bb[32 + k * 8];
                    breg[ntl][8 + 2 * k + 1] = bb[32 + k * 8 + 4];
                }
            }
            #pragma unroll 1
            for (int i = 0; i < 3; i++) {
                const int mt = mt0 + i;
                uint4 ahi[4];
                #pragma unroll
                for (int k = 0; k < 4; k++)
                    ahi[k] = __ldg(&g_Apack2[(mt * 12 + k) * 32 + lane]);
                float d0[4] = {0, 0, 0, 0}, d1[4] = {0, 0, 0, 0};
                #pragma unroll
                for (int k = 0; k < 4; k++) {
                    hmma(d0, ahi[k], breg[0][2 * k], breg[0][2 * k + 1]);
                    hmma(d1, ahi[k], breg[1][2 * k], breg[1][2 * k + 1]);
                }
                #pragma unroll
                for (int k = 0; k < 4; k++) {
                    const uint4 alo = __ldg(&g_Apack2[(mt * 12 + 4 + k) * 32 + lane]);
                    hmma(d0, alo, breg[0][2 * k], breg[0][2 * k + 1]);
                    hmma(d1, alo, breg[1][2 * k], breg[1][2 * k + 1]);
                }
                #pragma unroll
                for (int k = 0; k < 4; k++) {
                    hmma(d0, ahi[k], breg[0][8 + 2 * k], breg[0][8 + 2 * k + 1]);
                    hmma(d1, ahi[k], breg[1][8 + 2 * k], breg[1][8 + 2 * k + 1]);
                }
                const int r0 = mt * 16 + rg, r1 = r0 + 8;
                #pragma unroll
                for (int ntl = 0; ntl < 2; ntl++) {
                    float* d = ntl ? d1 : d0;
                    const int col = (nthalf * 4 + pass * 2 + ntl) * 8 + 2 * qd;
                    float v0 = d[0], v1 = d[1], v2 = d[2], v3 = d[3];
                    if (mt < 8) {
                        v0 = fminf(fmaxf(v0, -64.f), 64.f);
                        v1 = fminf(fmaxf(v1, -64.f), 64.f);
                        v2 = fminf(fmaxf(v2, -64.f), 64.f);
                        v3 = fminf(fmaxf(v3, -64.f), 64.f);
                    } else {
                        v0 = sigm2(v0);
                        v1 = sigm2(v1);
                        v2 = sigm2(v2);
                        v3 = sigm2(v3);
                    }
                    *reinterpret_cast<float2*>(&s_om[r0 * BW + col]) = make_float2(v0, v1);
                    *reinterpret_cast<float2*>(&s_om[r1 * BW + col]) = make_float2(v2, v3);
                }
            }
        }
    }
    __syncthreads();

    // ---- stage 3: bilinear sampling * modulator -> B tile (reused) --------
    {
        const int p  = 32 * (wid & 1) + lane;
        const int cb = (wid >> 1) * 16;
        #pragma unroll 4
        for (int i = 0; i < 8; i++) {
            const int c0 = cb + 2 * i;
            float v[2];
            #pragma unroll
            for (int s = 0; s < 2; s++) {
                const int c = c0 + s;
                const float offy = s_om[(2 * c)     * BW + p];
                const float offx = s_om[(2 * c + 1) * BW + p];
                const float md   = s_om[(128 + c)   * BW + p];
                const float sy = (float)h + offy;
                const float sx = (float)(w0 + p) + offx;
                const float y0f = floorf(sy);
                const float x0f = floorf(sx);
                const float wy = sy - y0f;
                const float wx = sx - x0f;
                const int y0  = (int)y0f;
                const int x0i = (int)x0f;
                const float* xc = x + ((size_t)(b * CC + c)) * (HH * WW);
                const float v00 = fetch_px(xc, y0,     x0i);
                const float v01 = fetch_px(xc, y0,     x0i + 1);
                const float v10 = fetch_px(xc, y0 + 1, x0i);
                const float v11 = fetch_px(xc, y0 + 1, x0i + 1);
                v[s] = ((1.0f - wy) * ((1.0f - wx) * v00 + wx * v01)
                      +         wy  * ((1.0f - wx) * v10 + wx * v11)) * md;
            }
            const __nv_bfloat16 h0 = __float2bfloat16(v[0]);
            const __nv_bfloat16 h1 = __float2bfloat16(v[1]);
            const __nv_bfloat16 l0 = __float2bfloat16(v[0] - __bfloat162float(h0));
            const __nv_bfloat16 l1 = __float2bfloat16(v[1] - __bfloat162float(h1));
            sB[p * BW + (c0 >> 1)]      = bfpack(h0, h1);
            sB[p * BW + 32 + (c0 >> 1)] = bfpack(l0, l1);
        }
    }
    __syncthreads();

    // ---- stage 4: out = w2 @ sampled (warp = 1 mt x 4 nt); BN partials ----
    {
        const int mt = wid & 3;
        const int r0 = mt * 16 + rg, r1 = r0 + 8;
        const float bz0 = __ldg(bias + r0);
        const float bz1 = __ldg(bias + r1);
        float sa0 = 0.f, sq0 = 0.f, sa1 = 0.f, sq1 = 0.f;

        #pragma unroll 1
        for (int pass = 0; pass < 2; pass++) {
            uint32_t breg[2][16];
            #pragma unroll
            for (int ntl = 0; ntl < 2; ntl++) {
                const int nt = nthalf * 4 + pass * 2 + ntl;
                const uint32_t* bb = sB + (nt * 8 + rg) * BW + qd;
                #pragma unroll
                for (int k = 0; k < 4; k++) {
                    breg[ntl][2 * k]         = bb[k * 8];
                    breg[ntl][2 * k + 1]     = bb[k * 8 + 4];
                    breg[ntl][8 + 2 * k]     = bb[32 + k * 8];
                    breg[ntl][8 + 2 * k + 1] = bb[32 + k * 8 + 4];
                }
            }
            uint4 ahi[4];
            #pragma unroll
            for (int k = 0; k < 4; k++)
                ahi[k] = __ldg(&g_Apack4[(mt * 12 + k) * 32 + lane]);
            float d0[4] = {0, 0, 0, 0}, d1[4] = {0, 0, 0, 0};
            #pragma unroll
            for (int k = 0; k < 4; k++) {
                hmma(d0, ahi[k], breg[0][2 * k], breg[0][2 * k + 1]);
                hmma(d1, ahi[k], breg[1][2 * k], breg[1][2 * k + 1]);
            }
            #pragma unroll
            for (int k = 0; k < 4; k++) {
                const uint4 alo = __ldg(&g_Apack4[(mt * 12 + 4 + k) * 32 + lane]);
                hmma(d0, alo, breg[0][2 * k], breg[0][2 * k + 1]);
                hmma(d1, alo, breg[1][2 * k], breg[1][2 * k + 1]);
            }
            #pragma unroll
            for (int k = 0; k < 4; k++) {
                hmma(d0, ahi[k], breg[0][8 + 2 * k], breg[0][8 + 2 * k + 1]);
                hmma(d1, ahi[k], breg[1][8 + 2 * k], breg[1][8 + 2 * k + 1]);
            }
            #pragma unroll
            for (int ntl = 0; ntl < 2; ntl++) {
                float* d = ntl ? d1 : d0;
                const int col = (nthalf * 4 + pass * 2 + ntl) * 8 + 2 * qd;
                const float v0 = d[0] + bz0, v1 = d[1] + bz0;
                const float v2 = d[2] + bz1, v3 = d[3] + bz1;
                float* o0 = out + (((size_t)(b * OCH + r0)) * HH + h) * WW + w0 + col;
                float* o1 = out + (((size_t)(b * OCH + r1)) * HH + h) * WW + w0 + col;
                *reinterpret_cast<float2*>(o0) = make_float2(v0, v1);
                *reinterpret_cast<float2*>(o1) = make_float2(v2, v3);
                sa0 += v0 + v1;  sq0 += v0 * v0 + v1 * v1;
                sa1 += v2 + v3;  sq1 += v2 * v2 + v3 * v3;
            }
        }
        #pragma unroll
        for (int m = 1; m <= 2; m <<= 1) {
            sa0 += __shfl_xor_sync(0xffffffffu, sa0, m);
            sq0 += __shfl_xor_sync(0xffffffffu, sq0, m);
            sa1 += __shfl_xor_sync(0xffffffffu, sa1, m);
            sq1 += __shfl_xor_sync(0xffffffffu, sq1, m);
        }
        if (qd == 0) {
            s_red [r0 * 2 + nthalf] = sa0;  s_red2[r0 * 2 + nthalf] = sq0;
            s_red [r1 * 2 + nthalf] = sa1;  s_red2[r1 * 2 + nthalf] = sq1;
        }
    }
    __syncthreads();

    if (tid < 64) {
        g_psum  [tid * NBLK + bid] = s_red [tid * 2] + s_red [tid * 2 + 1];
        g_psumsq[tid * NBLK + bid] = s_red2[tid * 2] + s_red2[tid * 2 + 1];
    }
}

// ---------------- BN stats + apply ------------------------------------------
__global__ void finalize_stats(const float* __restrict__ gamma,
                               const float* __restrict__ beta)
{
    const int o = blockIdx.x;
    __shared__ float ss[256];
    __shared__ float ss2[256];
    float s = 0.0f, s2 = 0.0f;
    for (int i = threadIdx.x; i < NBLK; i += 256) {
        s  += g_psum  [o * NBLK + i];
        s2 += g_psumsq[o * NBLK + i];
    }
    ss[threadIdx.x] = s; ss2[threadIdx.x] = s2;
    __syncthreads();
    for (int st = 128; st > 0; st >>= 1) {
        if (threadIdx.x < st) {
            ss [threadIdx.x] += ss [threadIdx.x + st];
            ss2[threadIdx.x] += ss2[threadIdx.x + st];
        }
        __syncthreads();
    }
    if (threadIdx.x == 0) {
        const float N = (float)(BB * HH * WW);
        const float mean = ss[0] / N;
        const float var  = ss2[0] / N - mean * mean;
        const float inv  = rsqrtf(var + 1e-5f);
        const float sc   = gamma[o] * inv;
        g_scale[o] = sc;
        g_shift[o] = beta[o] - mean * sc;
    }
}

// fast GELU (tanh form, saturating): max abs dev from exact ~3e-4
__device__ __forceinline__ float gelu_fast(float v) {
    const float t = 0.7978845608f * v * (1.0f + 0.044715f * v * v);
    const float e = __expf(2.0f * t);
    const float th = 1.0f - __fdividef(2.0f, e + 1.0f);
    return 0.5f * v * (1.0f + th);
}

__global__ __launch_bounds__(256)
void bn_gelu_kernel(float* __restrict__ out)
{
    // 2 float4 per thread, adjacent (same channel: plane = 65536 floats, 16384 f4)
    const int i = (blockIdx.x * blockDim.x + threadIdx.x) * 2;
    float4 va = reinterpret_cast<float4*>(out)[i];
    float4 vb = reinterpret_cast<float4*>(out)[i + 1];
    const int o = ((i * 4) >> 16) & 63;
    const float sc = g_scale[o];
    const float sh = g_shift[o];
    va.x = gelu_fast(va.x * sc + sh);
    va.y = gelu_fast(va.y * sc + sh);
    va.z = gelu_fast(va.z * sc + sh);
    va.w = gelu_fast(va.w * sc + sh);
    vb.x = gelu_fast(vb.x * sc + sh);
    vb.y = gelu_fast(vb.y * sc + sh);
    vb.z = gelu_fast(vb.z * sc + sh);
    vb.w = gelu_fast(vb.w * sc + sh);
    reinterpret_cast<float4*>(out)[i]     = va;
    reinterpret_cast<float4*>(out)[i + 1] = vb;
}

extern "C" void kernel_launch(void* const* d_in, const int* in_sizes, int n_in,
                              void* d_out, int out_size)
{
    const float* x     = (const float*)d_in[0];
    const float* dww   = (const float*)d_in[1];
    const float* pww   = (const float*)d_in[2];
    const float* w2    = (const float*)d_in[3];
    const float* bias  = (const float*)d_in[4];
    const float* gamma = (const float*)d_in[5];
    const float* beta  = (const float*)d_in[6];
    float* out = (float*)d_out;

    cudaFuncSetAttribute(fused_deform_kernel,
                         cudaFuncAttributeMaxDynamicSharedMemorySize, SMEM_BYTES);

    prep_weights<<<25, 256>>>(pww, w2, dww);
    dim3 grid(WW / PP, HH, BB);
    fused_deform_kernel<<<grid, 256, SMEM_BYTES>>>(x, bias, out);
    finalize_stats<<<OCH, 256>>>(gamma, beta);

    const int n8 = (BB * OCH * HH * WW) / 8;
    bn_gelu_kernel<<<n8 / 256, 256>>>(out);
}